// round 3
// baseline (speedup 1.0000x reference)
#include <cuda_runtime.h>
#include <math.h>

#define BB 2048
#define TT 2048
#define CC 8
#define AA 27
#define HH 8

// Scratch for per-sample conv kernel + bias (device globals: allowed, no alloc)
__device__ float g_ker[BB * CC];
__device__ float g_bias[BB];

__global__ void mlp_kernel(const float* __restrict__ attrs,
                           const float* __restrict__ w1,  const float* __restrict__ b1,
                           const float* __restrict__ w2,  const float* __restrict__ b2,
                           const float* __restrict__ bw1, const float* __restrict__ bb1,
                           const float* __restrict__ bw2, const float* __restrict__ bb2,
                           const float* __restrict__ mask_a,
                           const float* __restrict__ mask_h) {
    int b = blockIdx.x * blockDim.x + threadIdx.x;
    if (b >= BB) return;

    float a[AA];
#pragma unroll
    for (int i = 0; i < AA; i++)
        a[i] = attrs[b * AA + i] * mask_a[b * AA + i];

    float hw[HH], hb[HH];
#pragma unroll
    for (int h = 0; h < HH; h++) { hw[h] = b1[h]; hb[h] = bb1[h]; }

#pragma unroll
    for (int i = 0; i < AA; i++) {
        float ai = a[i];
#pragma unroll
        for (int h = 0; h < HH; h++) {
            hw[h] = fmaf(ai, w1[i * HH + h], hw[h]);
            hb[h] = fmaf(ai, bw1[i * HH + h], hb[h]);
        }
    }

#pragma unroll
    for (int h = 0; h < HH; h++) {
        float m = mask_h[b * HH + h];
        hw[h] = fmaxf(hw[h], 0.0f) * m;
        hb[h] = fmaxf(hb[h], 0.0f) * m;
    }

#pragma unroll
    for (int c = 0; c < CC; c++) {
        float s = b2[c];
#pragma unroll
        for (int h = 0; h < HH; h++)
            s = fmaf(hw[h], w2[h * CC + c], s);
        g_ker[b * CC + c] = tanhf(s);
    }

    float s = bb2[0];
#pragma unroll
    for (int h = 0; h < HH; h++)
        s = fmaf(hb[h], bw2[h], s);
    g_bias[b] = tanhf(s);
}

// One output element per thread. 8 blocks of 256 threads per batch row.
__global__ void __launch_bounds__(256) conv_kernel(const float* __restrict__ x,
                                                   float* __restrict__ out) {
    int b = blockIdx.x >> 3;                       // T/256 = 8 blocks per row
    int t = ((blockIdx.x & 7) << 8) + threadIdx.x; // 0..2047

    const float4* kp = (const float4*)(g_ker + b * CC);
    float4 k0 = kp[0];
    float4 k1 = kp[1];
    float bias = g_bias[b];

    const float4* xp = (const float4*)(x + ((long)b * TT + t) * CC);
    float4 x0 = xp[0];
    float4 x1 = xp[1];

    float y = bias;
    y = fmaf(x0.x, k0.x, y);
    y = fmaf(x0.y, k0.y, y);
    y = fmaf(x0.z, k0.z, y);
    y = fmaf(x0.w, k0.w, y);
    y = fmaf(x1.x, k1.x, y);
    y = fmaf(x1.y, k1.y, y);
    y = fmaf(x1.z, k1.z, y);
    y = fmaf(x1.w, k1.w, y);

    // ELU (alpha=1); expm1f avoids cancellation for y -> 0-
    float r = (y > 0.0f) ? y : expm1f(y);
    out[(long)b * TT + t] = r;
}

extern "C" void kernel_launch(void* const* d_in, const int* in_sizes, int n_in,
                              void* d_out, int out_size) {
    const float* x      = (const float*)d_in[0];
    const float* attrs  = (const float*)d_in[1];
    const float* w1     = (const float*)d_in[2];
    const float* b1     = (const float*)d_in[3];
    const float* w2     = (const float*)d_in[4];
    const float* b2     = (const float*)d_in[5];
    const float* bw1    = (const float*)d_in[6];
    const float* bb1    = (const float*)d_in[7];
    const float* bw2    = (const float*)d_in[8];
    const float* bb2    = (const float*)d_in[9];
    const float* mask_a = (const float*)d_in[10];
    const float* mask_h = (const float*)d_in[11];
    float* out = (float*)d_out;

    mlp_kernel<<<BB / 256, 256>>>(attrs, w1, b1, w2, b2, bw1, bb1, bw2, bb2,
                                  mask_a, mask_h);
    conv_kernel<<<BB * (TT / 256), 256>>>(x, out);
}